// round 5
// baseline (speedup 1.0000x reference)
#include <cuda_runtime.h>
#include <cstdint>
#include <cstddef>

typedef unsigned long long ull;

#define Dd 256
#define Tt 1024
#define Bb 64
#define HALF 128

// scratch: W = u @ Bm + b   (64 MB)
__device__ float g_W[(size_t)Bb * Tt * Dd];

// Dopri5 tableau (compile-time constants -> FFMA immediates)
__device__ constexpr float AT[6][6] = {
  {0,0,0,0,0,0},
  {0.2f,0,0,0,0,0},
  {0.075f,0.225f,0,0,0,0},
  {0.9777777777777777f,-3.7333333333333334f,3.5555555555555554f,0,0,0},
  {2.952598689224204f,-11.595793324188386f,9.822892851699436f,-0.2908093278463649f,0,0},
  {2.8462752525252526f,-10.757575757575758f,8.906422717743473f,0.2784090909090909f,-0.27353130360205833f,0}};
__device__ constexpr float BT[6] = {0.09114583333333333f,0.0f,0.4492362982929021f,
  0.6510416666666666f,-0.3223761792452830f,0.13095238095238096f};
// Hermite drive (t>=1): g = FM*W[t-1] + F0*W[t] + FP*W[t+1]
__device__ constexpr float FM[6] = {0.f,-0.128f,-0.147f,-0.032f,-0.010973936899862826f,0.f};
__device__ constexpr float F0[6] = {1.f, 1.056f, 0.994f, 0.264f, 0.13305898491083677f,0.f};
__device__ constexpr float FP[6] = {0.f, 0.072f, 0.153f, 0.768f, 0.8779149519890261f, 1.f};
// t == 0 (first-point derivative copy): g = C00*W[0] + C0P*W[1]
__device__ constexpr float C00[6] = {1.f,0.8f,0.7f,0.2f,0.1111111111111111f,0.f};
__device__ constexpr float C0P[6] = {0.f,0.2f,0.3f,0.8f,0.8888888888888888f,1.f};

// ---------------- helpers ----------------
__device__ __forceinline__ ull pk2(float lo, float hi) {
    ull r; asm("mov.b64 %0,{%1,%2};" : "=l"(r) : "f"(lo), "f"(hi)); return r;
}
__device__ __forceinline__ void fma2(ull& d, ull a, ull b) {
    asm("fma.rn.f32x2 %0,%1,%2,%0;" : "+l"(d) : "l"(a), "l"(b));
}
__device__ __forceinline__ ull add2(ull a, ull b) {
    ull r; asm("add.rn.f32x2 %0,%1,%2;" : "=l"(r) : "l"(a), "l"(b)); return r;
}
__device__ __forceinline__ float red2(ull a) {
    float lo, hi; asm("mov.b64 {%0,%1},%2;" : "=f"(lo), "=f"(hi) : "l"(a)); return lo + hi;
}
__device__ __forceinline__ float tanh_f(float x) {
    float e = __expf(2.0f * x);
    return 1.0f - __fdividef(2.0f, e + 1.0f);
}
__device__ __forceinline__ uint32_t smem_u32(const void* p) {
    uint32_t a;
    asm("{ .reg .u64 t; cvta.to.shared.u64 t, %1; cvt.u32.u64 %0, t; }"
        : "=r"(a) : "l"(p));
    return a;
}
__device__ __forceinline__ uint32_t mapa_u32(uint32_t a, uint32_t r) {
    uint32_t d; asm("mapa.shared::cluster.u32 %0, %1, %2;" : "=r"(d) : "r"(a), "r"(r));
    return d;
}
__device__ __forceinline__ void mbar_init(uint32_t a, uint32_t cnt) {
    asm volatile("mbarrier.init.shared.b64 [%0], %1;" :: "r"(a), "r"(cnt) : "memory");
}
__device__ __forceinline__ void sts_cluster_f32(uint32_t a, float v) {
    asm volatile("st.shared::cluster.f32 [%0], %1;" :: "r"(a), "f"(v) : "memory");
}
__device__ __forceinline__ void mbar_arrive_rel_cluster(uint32_t a) {
    asm volatile("mbarrier.arrive.release.cluster.shared::cluster.b64 _, [%0];"
                 :: "r"(a) : "memory");
}
__device__ __forceinline__ void wait_parity_cluster(uint32_t a, uint32_t parity) {
    asm volatile(
        "{\n\t.reg .pred P;\n\t"
        "W%=:\n\t"
        "mbarrier.try_wait.parity.acquire.cluster.shared::cta.b64 P, [%0], %1, 0x989680;\n\t"
        "@!P bra W%=;\n\t}"
        :: "r"(a), "r"(parity) : "memory");
}
__device__ __forceinline__ void cluster_sync_() {
    asm volatile("barrier.cluster.arrive.aligned;" ::: "memory");
    asm volatile("barrier.cluster.wait.aligned;" ::: "memory");
}
__device__ __forceinline__ void bar_named(int id) {
    asm volatile("bar.sync %0, 128;" :: "r"(id) : "memory");
}

// ================ sequential Dopri5 flow ================
// Cluster of 2 CTAs per batch element; 256 thr: lc = tid&127 (A column
// rank*128+lc), h = tid>>7 (A row half). Early group (h==rank) keeps its own
// column's k in registers and never waits; late group (h!=rank) waits for the
// peer's k via direct st.shared::cluster + mbarrier (release/acquire).
__global__ void __launch_bounds__(256, 1) __cluster_dims__(2, 1, 1)
flow_kernel(const float* __restrict__ tarr, const float* __restrict__ x0,
            const float* __restrict__ Amat, const float* __restrict__ W,
            float* __restrict__ xtraj)
{
    __shared__ __align__(16) float xsh[Dd];          // stage state (full)
    __shared__ float psh[HALF];                      // late-half dot partials
    __shared__ __align__(16) float kdt_sh[2][6*HALF];// peer-written dt*k, by t-parity
    __shared__ __align__(8)  ull  mbar[6];

    const int tid = threadIdx.x;
    const int lc  = tid & (HALF - 1);
    const int h   = tid >> 7;
    uint32_t rank; asm("mov.u32 %0, %%cluster_ctarank;" : "=r"(rank));
    const uint32_t peer = rank ^ 1u;
    const int b   = blockIdx.x >> 1;
    const int acol = (int)rank * HALF + lc;          // this thread's dot column
    const bool isE = (h == (int)rank);
    const float dt = tarr[1] - tarr[0];

    const uint32_t mbar_a  = smem_u32(mbar);
    const uint32_t kdt_a   = smem_u32(kdt_sh);
    const uint32_t peer_k  = mapa_u32(kdt_a, peer);
    const uint32_t peer_mb = mapa_u32(mbar_a, peer);

    if (tid < 6) mbar_init(mbar_a + 8u*(uint32_t)tid, 128);
    __syncthreads();
    cluster_sync_();

    // A slice: rows [h*128, h*128+128), column acol -> 64 packed pairs (128 regs)
    ull Ar[64];
#pragma unroll
    for (int p = 0; p < 64; ++p)
        Ar[p] = pk2(Amat[(h*HALF + 2*p)*Dd + acol],
                    Amat[(h*HALF + 2*p + 1)*Dd + acol]);

    float xr = x0[b*Dd + tid];                  // state at column tid
    if (isE) xtraj[(size_t)b*Tt*Dd + tid] = xr;

    const float* Wb = W + (size_t)b*Tt*Dd + tid;  // E threads only (col == tid)
    float w0 = 0.f, wp = 0.f, wm = 0.f;
    if (isE) { w0 = Wb[0]; wp = Wb[Dd]; }

    float kdt[6];                                // dt * k for own column (E)
#pragma unroll
    for (int i = 0; i < 6; ++i) kdt[i] = 0.f;

    for (int t = 0; t < Tt - 1; ++t) {
        const uint32_t par = (uint32_t)(t & 1);
        const bool fst = (t == 0);
        const float* kp = kdt_sh[par];

#pragma unroll
        for (int j = 0; j < 6; ++j) {
            float xs = xr;
            if (isE) {
#pragma unroll
                for (int i = 0; i < j; ++i)
                    if (AT[j][i] != 0.0f) xs += AT[j][i] * kdt[i];
            } else {
                if (j > 0) wait_parity_cluster(mbar_a + 8u*(j-1), par);
#pragma unroll
                for (int i = 0; i < j; ++i)
                    if (AT[j][i] != 0.0f) xs += AT[j][i] * kp[i*HALF + lc];
            }
            xsh[tid] = xs;
            // drive term (off critical path: only needs w-registers)
            float g = fst ? (C00[j]*w0 + C0P[j]*wp)
                          : (FM[j]*wm + F0[j]*w0 + FP[j]*wp);
            bar_named(1 + h);                    // own half's xs complete

            // 128-row dot for column acol (A in regs, broadcast x from smem)
            const ulonglong2* xv = (const ulonglong2*)(xsh + h*HALF);
            ull a0 = 0, a1 = 0, a2 = 0, a3 = 0;
#pragma unroll
            for (int q = 0; q < 32; q += 2) {
                ulonglong2 v0 = xv[q], v1 = xv[q + 1];
                fma2(a0, v0.x, Ar[2*q    ]); fma2(a1, v0.y, Ar[2*q + 1]);
                fma2(a2, v1.x, Ar[2*q + 2]); fma2(a3, v1.y, Ar[2*q + 3]);
            }
            float part = red2(add2(add2(a0, a1), add2(a2, a3)));

            if (!isE) psh[lc] = part;
            __syncthreads();
            if (isE) {
                float kv = tanh_f(part + psh[lc] + g);
                float kd = dt * kv;
                kdt[j] = kd;
                // ship dt*k to the peer's late half + release-arrive
                sts_cluster_f32(peer_k + ((par*6u + (uint32_t)j)*HALF + (uint32_t)lc)*4u, kd);
                mbar_arrive_rel_cluster(peer_mb + 8u*(uint32_t)j);
            }
        }

        if (isE) {
            xr += BT[0]*kdt[0] + BT[2]*kdt[2] + BT[3]*kdt[3]
                + BT[4]*kdt[4] + BT[5]*kdt[5];
            xtraj[(size_t)b*Tt*Dd + (size_t)(t + 1)*Dd + tid] = xr;
            wm = w0; w0 = wp;
            if (t < Tt - 2) wp = Wb[(size_t)(t + 2)*Dd];
        } else {
            wait_parity_cluster(mbar_a + 8u*5, par);
            xr += BT[0]*kp[0*HALF + lc] + BT[2]*kp[2*HALF + lc]
                + BT[3]*kp[3*HALF + lc] + BT[4]*kp[4*HALF + lc]
                + BT[5]*kp[5*HALF + lc];
        }
    }
    cluster_sync_();   // no CTA exits while peer stores may be in flight
}

// Out[M,N] = A[M,K] @ B[K,N] (+ bias). 64x64 tile, BK=16, 256 thr, 4x4/thread.
__global__ void __launch_bounds__(256)
gemm_kernel(const float* __restrict__ A, const float* __restrict__ B,
            const float* __restrict__ bias, float* __restrict__ out,
            int K, int N)
{
    __shared__ float As[16][68];
    __shared__ float Bs[16][68];
    const int tid = threadIdx.x;
    const int tx = tid & 15, ty = tid >> 4;
    const int m0 = blockIdx.y * 64;
    const int n0 = blockIdx.x * 64;
    const int arow = tid >> 2, aq = tid & 3;
    const int brow = tid >> 4, bq = tid & 15;

    float acc[4][4] = {};
    for (int k0 = 0; k0 < K; k0 += 16) {
        float4 av = *(const float4*)&A[(size_t)(m0 + arow)*K + k0 + 4*aq];
        As[4*aq+0][arow] = av.x; As[4*aq+1][arow] = av.y;
        As[4*aq+2][arow] = av.z; As[4*aq+3][arow] = av.w;
        float4 bv = *(const float4*)&B[(size_t)(k0 + brow)*N + n0 + 4*bq];
        *(float4*)&Bs[brow][4*bq] = bv;
        __syncthreads();
#pragma unroll
        for (int k = 0; k < 16; ++k) {
            float a[4], bb[4];
#pragma unroll
            for (int i = 0; i < 4; ++i) a[i] = As[k][ty*4 + i];
#pragma unroll
            for (int jj = 0; jj < 4; ++jj) bb[jj] = Bs[k][tx*4 + jj];
#pragma unroll
            for (int i = 0; i < 4; ++i)
#pragma unroll
                for (int jj = 0; jj < 4; ++jj) acc[i][jj] += a[i]*bb[jj];
        }
        __syncthreads();
    }
#pragma unroll
    for (int i = 0; i < 4; ++i) {
        const int m = m0 + ty*4 + i;
#pragma unroll
        for (int jj = 0; jj < 4; ++jj) {
            const int n = n0 + tx*4 + jj;
            float v = acc[i][jj];
            if (bias) v += bias[n];
            out[(size_t)m*N + n] = v;
        }
    }
}

extern "C" void kernel_launch(void* const* d_in, const int* in_sizes, int n_in,
                              void* d_out, int out_size)
{
    const float* tarr = (const float*)d_in[0];   // (1024,)
    const float* u    = (const float*)d_in[1];   // (64,1024,128)
    const float* x0   = (const float*)d_in[2];   // (64,256)
    const float* Amat = (const float*)d_in[3];   // (256,256)
    const float* Bm   = (const float*)d_in[4];   // (128,256)
    const float* bias = (const float*)d_in[5];   // (256,)
    const float* Cm   = (const float*)d_in[6];   // (256,64)

    float* out   = (float*)d_out;
    float* xtraj = out;                              // (64,1024,256)
    float* y     = out + (size_t)Bb * Tt * Dd;       // (64,1024,64)

    float* W = nullptr;
    cudaGetSymbolAddress((void**)&W, g_W);

    // 1) W[b,t,:] = u[b,t,:] @ Bm + bias    M=65536, K=128, N=256
    gemm_kernel<<<dim3(Dd/64, (Bb*Tt)/64), 256>>>(u, Bm, bias, W, 128, Dd);

    // 2) sequential Dopri5 flow: 64 batches x 2-CTA clusters = 128 CTAs
    flow_kernel<<<2*Bb, 256>>>(tarr, x0, Amat, W, xtraj);

    // 3) y = x_traj @ C                     M=65536, K=256, N=64
    gemm_kernel<<<dim3(1, (Bb*Tt)/64), 256>>>(xtraj, Cm, nullptr, y, Dd, 64);
}

// round 7
// speedup vs baseline: 1.2529x; 1.2529x over previous
#include <cuda_runtime.h>
#include <cstdint>
#include <cstddef>

typedef unsigned long long ull;

#define Dd 256
#define Tt 1024
#define Bb 64
#define HALF 128

// scratch: W = u @ Bm + b   (64 MB)
__device__ float g_W[(size_t)Bb * Tt * Dd];

// Dopri5 tableau (compile-time constants -> FFMA immediates)
__device__ constexpr float AT[6][6] = {
  {0,0,0,0,0,0},
  {0.2f,0,0,0,0,0},
  {0.075f,0.225f,0,0,0,0},
  {0.9777777777777777f,-3.7333333333333334f,3.5555555555555554f,0,0,0},
  {2.952598689224204f,-11.595793324188386f,9.822892851699436f,-0.2908093278463649f,0,0},
  {2.8462752525252526f,-10.757575757575758f,8.906422717743473f,0.2784090909090909f,-0.27353130360205833f,0}};
__device__ constexpr float BT[6] = {0.09114583333333333f,0.0f,0.4492362982929021f,
  0.6510416666666666f,-0.3223761792452830f,0.13095238095238096f};
// Hermite drive (t>=1): g = FM*W[t-1] + F0*W[t] + FP*W[t+1]
__device__ constexpr float FM[6] = {0.f,-0.128f,-0.147f,-0.032f,-0.010973936899862826f,0.f};
__device__ constexpr float F0[6] = {1.f, 1.056f, 0.994f, 0.264f, 0.13305898491083677f,0.f};
__device__ constexpr float FP[6] = {0.f, 0.072f, 0.153f, 0.768f, 0.8779149519890261f, 1.f};
// t == 0 (first-point derivative copy): g = C00*W[0] + C0P*W[1]
__device__ constexpr float C00[6] = {1.f,0.8f,0.7f,0.2f,0.1111111111111111f,0.f};
__device__ constexpr float C0P[6] = {0.f,0.2f,0.3f,0.8f,0.8888888888888888f,1.f};

// ---------------- helpers ----------------
__device__ __forceinline__ ull pk2(float lo, float hi) {
    ull r; asm("mov.b64 %0,{%1,%2};" : "=l"(r) : "f"(lo), "f"(hi)); return r;
}
__device__ __forceinline__ void fma2(ull& d, ull a, ull b) {
    asm("fma.rn.f32x2 %0,%1,%2,%0;" : "+l"(d) : "l"(a), "l"(b));
}
__device__ __forceinline__ ull add2(ull a, ull b) {
    ull r; asm("add.rn.f32x2 %0,%1,%2;" : "=l"(r) : "l"(a), "l"(b)); return r;
}
__device__ __forceinline__ float red2(ull a) {
    float lo, hi; asm("mov.b64 {%0,%1},%2;" : "=f"(lo), "=f"(hi) : "l"(a)); return lo + hi;
}
__device__ __forceinline__ float tanh_f(float x) {
    float e = __expf(2.0f * x);
    return 1.0f - __fdividef(2.0f, e + 1.0f);
}
__device__ __forceinline__ uint32_t smem_u32(const void* p) {
    uint32_t a;
    asm("{ .reg .u64 t; cvta.to.shared.u64 t, %1; cvt.u32.u64 %0, t; }"
        : "=r"(a) : "l"(p));
    return a;
}
__device__ __forceinline__ uint32_t mapa_u32(uint32_t a, uint32_t r) {
    uint32_t d; asm("mapa.shared::cluster.u32 %0, %1, %2;" : "=r"(d) : "r"(a), "r"(r));
    return d;
}
__device__ __forceinline__ void mbar_init(uint32_t a, uint32_t cnt) {
    asm volatile("mbarrier.init.shared.b64 [%0], %1;" :: "r"(a), "r"(cnt) : "memory");
}
__device__ __forceinline__ void mbar_arm(uint32_t a, uint32_t bytes) {
    asm volatile("mbarrier.arrive.expect_tx.shared.b64 _, [%0], %1;"
                 :: "r"(a), "r"(bytes) : "memory");
}
// async store to peer smem; tx-completion credited to peer's mbarrier
__device__ __forceinline__ void st_async_f32(uint32_t dst, float v, uint32_t rbar) {
    asm volatile(
        "st.async.shared::cluster.mbarrier::complete_tx::bytes.f32 [%0], %1, [%2];"
        :: "r"(dst), "f"(v), "r"(rbar) : "memory");
}
__device__ __forceinline__ void wait_parity(uint32_t a, uint32_t parity) {
    asm volatile(
        "{\n\t.reg .pred P;\n\t"
        "W%=:\n\t"
        "mbarrier.try_wait.parity.acquire.cta.shared::cta.b64 P, [%0], %1, 0x989680;\n\t"
        "@!P bra W%=;\n\t}"
        :: "r"(a), "r"(parity) : "memory");
}
__device__ __forceinline__ void cluster_sync_() {
    asm volatile("barrier.cluster.arrive.aligned;" ::: "memory");
    asm volatile("barrier.cluster.wait.aligned;" ::: "memory");
}

// 128-row partial dot: rows from Ar (regs), k from smem (broadcast reads)
__device__ __forceinline__ float pdot(const float* __restrict__ kbuf,
                                      const ull (&Ar)[64])
{
    const ulonglong2* xv = (const ulonglong2*)kbuf;
    ull a0 = 0, a1 = 0, a2 = 0, a3 = 0;
#pragma unroll
    for (int q = 0; q < 32; q += 2) {
        ulonglong2 v0 = xv[q], v1 = xv[q + 1];
        fma2(a0, v0.x, Ar[2*q    ]); fma2(a1, v0.y, Ar[2*q + 1]);
        fma2(a2, v1.x, Ar[2*q + 2]); fma2(a3, v1.y, Ar[2*q + 3]);
    }
    return red2(add2(add2(a0, a1), add2(a2, a3)));
}

// ================ sequential Dopri5 flow ================
// 2-CTA cluster per batch element, ROW-split A (each CTA: rows
// [rank*128, rank*128+128) x all 256 cols, fully register-resident).
// k / z / x are replicated per-column across both CTAs (elementwise ops);
// only the 128-row partial GEMV sums cross the fabric (1KB st.async/stage).
__global__ void __launch_bounds__(256, 1) __cluster_dims__(2, 1, 1)
flow_kernel(const float* __restrict__ tarr, const float* __restrict__ x0,
            const float* __restrict__ Amat, const float* __restrict__ W,
            float* __restrict__ xtraj)
{
    __shared__ __align__(16) float ksh[2][Dd];   // dt*k staging, stage-parity buffers
    __shared__ __align__(16) float pvd[7][Dd];   // peer partial sums (slot 6 = init)
    __shared__ __align__(8)  ull  mbar[7];

    const int c = threadIdx.x;                   // this thread's column
    uint32_t rank; asm("mov.u32 %0, %%cluster_ctarank;" : "=r"(rank));
    const uint32_t peer = rank ^ 1u;
    const int b = blockIdx.x >> 1;
    const float dt = tarr[1] - tarr[0];

    const uint32_t mbar_a = smem_u32(mbar);
    const uint32_t pvd_a  = smem_u32(pvd);
    const uint32_t peer_pvd = mapa_u32(pvd_a, peer);
    const uint32_t peer_mb  = mapa_u32(mbar_a, peer);

    if (c == 0) {
        for (int j = 0; j < 7; ++j) mbar_init(mbar_a + 8u*j, 1);
    }
    __syncthreads();
    if (c == 0) {
        for (int j = 0; j < 7; ++j) mbar_arm(mbar_a + 8u*j, Dd*4);  // 1KB/phase
    }
    __syncthreads();
    cluster_sync_();   // mbarriers armed cluster-wide before any st.async

    // A rows [rank*128, +128) for column c -> 64 packed pairs (128 regs)
    ull Ar[64];
#pragma unroll
    for (int p = 0; p < 64; ++p)
        Ar[p] = pk2(Amat[((int)rank*HALF + 2*p)*Dd + c],
                    Amat[((int)rank*HALF + 2*p + 1)*Dd + c]);

    float xr = x0[b*Dd + c];                 // replicated full state
    if ((c >> 7) == (int)rank)
        xtraj[(size_t)b*Tt*Dd + c] = xr;     // each CTA writes its column half

    const float* Wb = W + (size_t)b*Tt*Dd + c;
    float w0 = Wb[0], wp = Wb[Dd], wm = 0.f;

    // ---- init: z = (A^T x0)[c] via one partial-exchange (slot 6, buffer 1) ----
    ksh[1][c] = xr;
    __syncthreads();
    {
        float pv = pdot(ksh[1] + (int)rank*HALF, Ar);
        st_async_f32(peer_pvd + (6u*Dd + (uint32_t)c)*4u, pv, peer_mb + 8u*6);
        wait_parity(mbar_a + 8u*6, 0);
    }
    float z = pdot(ksh[1] + (int)rank*HALF, Ar) * 0.f;  // placeholder overwritten below
    z = pvd[6][c] + pdot(ksh[1] + (int)rank*HALF, Ar);  // pv recomputed cheaply? no:
    // (recompute avoided: fold into one expression)
    // NOTE: the two lines above are redundant-safe but wasteful; compute once:
    // -- replaced by the block below --

    // clean single computation of z (the above kept minimal; recompute partial once)
    // z = own partial + peer partial:
    // (own partial recomputed deterministically from unchanged ksh[1])

    for (int t = 0; t < Tt - 1; ++t) {
        const uint32_t par = (uint32_t)(t & 1);
        const bool fst = (t == 0);
        float kdt[6], vd[6];

#pragma unroll
        for (int j = 0; j < 6; ++j) {
            const int jj = j & 1;
            float part = z;
#pragma unroll
            for (int i = 0; i < j; ++i)
                if (AT[j][i] != 0.0f) part += AT[j][i] * vd[i];
            float g = fst ? (C00[j]*w0 + C0P[j]*wp)
                          : (FM[j]*wm + F0[j]*w0 + FP[j]*wp);
            float kd = dt * tanh_f(part + g);
            kdt[j] = kd;
            ksh[jj][c] = kd;
            __syncthreads();

            float pv = pdot(ksh[jj] + (int)rank*HALF, Ar);
            st_async_f32(peer_pvd + ((uint32_t)j*Dd + (uint32_t)c)*4u,
                         pv, peer_mb + 8u*(uint32_t)j);
            wait_parity(mbar_a + 8u*(uint32_t)j, par);
            if (c == 0) mbar_arm(mbar_a + 8u*(uint32_t)j, Dd*4);  // re-arm next phase
            vd[j] = pv + pvd[j][c];
        }

        xr += BT[0]*kdt[0] + BT[2]*kdt[2] + BT[3]*kdt[3]
            + BT[4]*kdt[4] + BT[5]*kdt[5];
        z  += BT[0]*vd[0] + BT[2]*vd[2] + BT[3]*vd[3]
            + BT[4]*vd[4] + BT[5]*vd[5];
        if ((c >> 7) == (int)rank)
            xtraj[(size_t)b*Tt*Dd + (size_t)(t + 1)*Dd + c] = xr;

        wm = w0; w0 = wp;
        if (t < Tt - 2) wp = Wb[(size_t)(t + 2)*Dd];
    }
    cluster_sync_();   // no CTA exits while peer st.async may be in flight
}

// Out[M,N] = A[M,K] @ B[K,N] (+ bias). 64x64 tile, BK=16, 256 thr, 4x4/thread.
__global__ void __launch_bounds__(256)
gemm_kernel(const float* __restrict__ A, const float* __restrict__ B,
            const float* __restrict__ bias, float* __restrict__ out,
            int K, int N)
{
    __shared__ float As[16][68];
    __shared__ float Bs[16][68];
    const int tid = threadIdx.x;
    const int tx = tid & 15, ty = tid >> 4;
    const int m0 = blockIdx.y * 64;
    const int n0 = blockIdx.x * 64;
    const int arow = tid >> 2, aq = tid & 3;
    const int brow = tid >> 4, bq = tid & 15;

    float acc[4][4] = {};
    for (int k0 = 0; k0 < K; k0 += 16) {
        float4 av = *(const float4*)&A[(size_t)(m0 + arow)*K + k0 + 4*aq];
        As[4*aq+0][arow] = av.x; As[4*aq+1][arow] = av.y;
        As[4*aq+2][arow] = av.z; As[4*aq+3][arow] = av.w;
        float4 bv = *(const float4*)&B[(size_t)(k0 + brow)*N + n0 + 4*bq];
        *(float4*)&Bs[brow][4*bq] = bv;
        __syncthreads();
#pragma unroll
        for (int k = 0; k < 16; ++k) {
            float a[4], bb[4];
#pragma unroll
            for (int i = 0; i < 4; ++i) a[i] = As[k][ty*4 + i];
#pragma unroll
            for (int jj = 0; jj < 4; ++jj) bb[jj] = Bs[k][tx*4 + jj];
#pragma unroll
            for (int i = 0; i < 4; ++i)
#pragma unroll
                for (int jj = 0; jj < 4; ++jj) acc[i][jj] += a[i]*bb[jj];
        }
        __syncthreads();
    }
#pragma unroll
    for (int i = 0; i < 4; ++i) {
        const int m = m0 + ty*4 + i;
#pragma unroll
        for (int jj = 0; jj < 4; ++jj) {
            const int n = n0 + tx*4 + jj;
            float v = acc[i][jj];
            if (bias) v += bias[n];
            out[(size_t)m*N + n] = v;
        }
    }
}

extern "C" void kernel_launch(void* const* d_in, const int* in_sizes, int n_in,
                              void* d_out, int out_size)
{
    const float* tarr = (const float*)d_in[0];   // (1024,)
    const float* u    = (const float*)d_in[1];   // (64,1024,128)
    const float* x0   = (const float*)d_in[2];   // (64,256)
    const float* Amat = (const float*)d_in[3];   // (256,256)
    const float* Bm   = (const float*)d_in[4];   // (128,256)
    const float* bias = (const float*)d_in[5];   // (256,)
    const float* Cm   = (const float*)d_in[6];   // (256,64)

    float* out   = (float*)d_out;
    float* xtraj = out;                              // (64,1024,256)
    float* y     = out + (size_t)Bb * Tt * Dd;       // (64,1024,64)

    float* W = nullptr;
    cudaGetSymbolAddress((void**)&W, g_W);

    // 1) W[b,t,:] = u[b,t,:] @ Bm + bias    M=65536, K=128, N=256
    gemm_kernel<<<dim3(Dd/64, (Bb*Tt)/64), 256>>>(u, Bm, bias, W, 128, Dd);

    // 2) sequential Dopri5 flow: 64 batches x 2-CTA clusters = 128 CTAs
    flow_kernel<<<2*Bb, 256>>>(tarr, x0, Amat, W, xtraj);

    // 3) y = x_traj @ C                     M=65536, K=256, N=64
    gemm_kernel<<<dim3(1, (Bb*Tt)/64), 256>>>(xtraj, Cm, nullptr, y, Dd, 64);
}

// round 10
// speedup vs baseline: 1.4354x; 1.1457x over previous
#include <cuda_runtime.h>
#include <cstdint>
#include <cstddef>

typedef unsigned long long ull;

#define Dd 256
#define Tt 1024
#define Bb 64
#define HALF 128

// scratch: W = u @ Bm + b   (64 MB)
__device__ float g_W[(size_t)Bb * Tt * Dd];

// Dopri5 tableau (compile-time constants -> FFMA immediates)
__device__ constexpr float AT[6][6] = {
  {0,0,0,0,0,0},
  {0.2f,0,0,0,0,0},
  {0.075f,0.225f,0,0,0,0},
  {0.9777777777777777f,-3.7333333333333334f,3.5555555555555554f,0,0,0},
  {2.952598689224204f,-11.595793324188386f,9.822892851699436f,-0.2908093278463649f,0,0},
  {2.8462752525252526f,-10.757575757575758f,8.906422717743473f,0.2784090909090909f,-0.27353130360205833f,0}};
__device__ constexpr float BT[6] = {0.09114583333333333f,0.0f,0.4492362982929021f,
  0.6510416666666666f,-0.3223761792452830f,0.13095238095238096f};
// Hermite drive (t>=1): g = FM*W[t-1] + F0*W[t] + FP*W[t+1]
__device__ constexpr float FM[6] = {0.f,-0.128f,-0.147f,-0.032f,-0.010973936899862826f,0.f};
__device__ constexpr float F0[6] = {1.f, 1.056f, 0.994f, 0.264f, 0.13305898491083677f,0.f};
__device__ constexpr float FP[6] = {0.f, 0.072f, 0.153f, 0.768f, 0.8779149519890261f, 1.f};
// t == 0 (first-point derivative copy): g = C00*W[0] + C0P*W[1]
__device__ constexpr float C00[6] = {1.f,0.8f,0.7f,0.2f,0.1111111111111111f,0.f};
__device__ constexpr float C0P[6] = {0.f,0.2f,0.3f,0.8f,0.8888888888888888f,1.f};

// ---------------- helpers ----------------
__device__ __forceinline__ ull pk2(float lo, float hi) {
    ull r; asm("mov.b64 %0,{%1,%2};" : "=l"(r) : "f"(lo), "f"(hi)); return r;
}
__device__ __forceinline__ void fma2(ull& d, ull a, ull b) {
    asm("fma.rn.f32x2 %0,%1,%2,%0;" : "+l"(d) : "l"(a), "l"(b));
}
__device__ __forceinline__ ull add2(ull a, ull b) {
    ull r; asm("add.rn.f32x2 %0,%1,%2;" : "=l"(r) : "l"(a), "l"(b)); return r;
}
__device__ __forceinline__ float red2(ull a) {
    float lo, hi; asm("mov.b64 {%0,%1},%2;" : "=f"(lo), "=f"(hi) : "l"(a)); return lo + hi;
}
__device__ __forceinline__ float tanh_f(float x) {
    float e = __expf(2.0f * x);
    return 1.0f - __fdividef(2.0f, e + 1.0f);
}
__device__ __forceinline__ uint32_t smem_u32(const void* p) {
    uint32_t a;
    asm("{ .reg .u64 t; cvta.to.shared.u64 t, %1; cvt.u32.u64 %0, t; }"
        : "=r"(a) : "l"(p));
    return a;
}
__device__ __forceinline__ uint32_t mapa_u32(uint32_t a, uint32_t r) {
    uint32_t d; asm("mapa.shared::cluster.u32 %0, %1, %2;" : "=r"(d) : "r"(a), "r"(r));
    return d;
}
__device__ __forceinline__ void mbar_init(uint32_t a, uint32_t cnt) {
    asm volatile("mbarrier.init.shared.b64 [%0], %1;" :: "r"(a), "r"(cnt) : "memory");
}
__device__ __forceinline__ void mbar_arm(uint32_t a, uint32_t bytes) {
    asm volatile("mbarrier.arrive.expect_tx.shared.b64 _, [%0], %1;"
                 :: "r"(a), "r"(bytes) : "memory");
}
__device__ __forceinline__ void st_async_f32(uint32_t dst, float v, uint32_t rbar) {
    asm volatile(
        "st.async.shared::cluster.mbarrier::complete_tx::bytes.f32 [%0], %1, [%2];"
        :: "r"(dst), "f"(v), "r"(rbar) : "memory");
}
__device__ __forceinline__ void wait_parity(uint32_t a, uint32_t parity) {
    asm volatile(
        "{\n\t.reg .pred P;\n\t"
        "W%=:\n\t"
        "mbarrier.try_wait.parity.acquire.cta.shared::cta.b64 P, [%0], %1, 0x989680;\n\t"
        "@!P bra W%=;\n\t}"
        :: "r"(a), "r"(parity) : "memory");
}
__device__ __forceinline__ void cluster_sync_() {
    asm volatile("barrier.cluster.arrive.aligned;" ::: "memory");
    asm volatile("barrier.cluster.wait.aligned;" ::: "memory");
}

// 128-row partial dot: rows from Ar (regs), k from smem (broadcast reads)
__device__ __forceinline__ float pdot(const float* __restrict__ kbuf,
                                      const ull (&Ar)[64])
{
    const ulonglong2* xv = (const ulonglong2*)kbuf;
    ull a0 = 0, a1 = 0, a2 = 0, a3 = 0;
#pragma unroll
    for (int q = 0; q < 32; q += 2) {
        ulonglong2 v0 = xv[q], v1 = xv[q + 1];
        fma2(a0, v0.x, Ar[2*q    ]); fma2(a1, v0.y, Ar[2*q + 1]);
        fma2(a2, v1.x, Ar[2*q + 2]); fma2(a3, v1.y, Ar[2*q + 3]);
    }
    return red2(add2(add2(a0, a1), add2(a2, a3)));
}

// ================ sequential Dopri5 flow ================
// 2-CTA cluster per batch. COLUMN-split state: CTA r owns columns
// [r*128, r*128+128). 256 threads = 128 cols x 2 row-halves (ro = tid>>7).
// A[:, own cols] fully register-resident (64 ull per thread). Per stage only
// the owner-computed dt*k half (512B) crosses the fabric (st.async +
// complete_tx). Early threads (ro==rank) dot the locally-staged k half while
// the peer half is in flight; late threads wait the mbarrier then dot.
__global__ void __launch_bounds__(256, 1) __cluster_dims__(2, 1, 1)
flow_kernel(const float* __restrict__ tarr, const float* __restrict__ x0,
            const float* __restrict__ Amat, const float* __restrict__ W,
            float* __restrict__ xtraj)
{
    __shared__ __align__(16) float ksh[6][Dd];   // staged dt*k (full vector), slot per stage
    __shared__ float psh[HALF];                  // ro=1 partials
    __shared__ __align__(8)  ull  mbar[6];

    const int tid = threadIdx.x;
    const int lc  = tid & (HALF - 1);
    const int ro  = tid >> 7;                    // row half
    uint32_t rank; asm("mov.u32 %0, %%cluster_ctarank;" : "=r"(rank));
    const uint32_t peer = rank ^ 1u;
    const int b   = blockIdx.x >> 1;
    const int col = (int)rank * HALF + lc;       // owned column (ro==0 threads)
    const bool isE     = (ro == (int)rank);      // early dot (local k half)
    const bool isOwner = (ro == 0);
    const int lateFirst = (rank == 0) ? HALF : 0;
    const float dt = tarr[1] - tarr[0];

    const uint32_t mbar_a = smem_u32(mbar);
    const uint32_t ksh_a  = smem_u32(ksh);
    const uint32_t peer_ksh = mapa_u32(ksh_a, peer);
    const uint32_t peer_mb  = mapa_u32(mbar_a, peer);

    if (tid < 6) mbar_init(mbar_a + 8u*(uint32_t)tid, 1);
    __syncthreads();
    if (tid < 6) mbar_arm(mbar_a + 8u*(uint32_t)tid, HALF*4);   // 512B per phase
    __syncthreads();
    cluster_sync_();     // armed cluster-wide before any st.async

    // A rows [ro*128, +128) of owned column -> 64 packed pairs (128 regs)
    ull Ar[64];
#pragma unroll
    for (int p = 0; p < 64; ++p)
        Ar[p] = pk2(Amat[(ro*HALF + 2*p)*Dd + col],
                    Amat[(ro*HALF + 2*p + 1)*Dd + col]);

    // owner-only state
    float xr = 0.f, z = 0.f, w0 = 0.f, wp = 0.f, wm = 0.f;
    float kdreg[6], vdj[6];
#pragma unroll
    for (int i = 0; i < 6; ++i) { kdreg[i] = 0.f; vdj[i] = 0.f; }
    const float* Wb = W + (size_t)b*Tt*Dd + col;
    if (isOwner) {
        xr = x0[b*Dd + col];
        w0 = Wb[0]; wp = Wb[Dd];
        xtraj[(size_t)b*Tt*Dd + col] = xr;
    }

    // ---- init: z = (A^T x0)[col] (both halves local; no fabric) ----
    ksh[0][tid] = x0[b*Dd + tid];
    __syncthreads();
    {
        float part = pdot(ksh[0] + ro*HALF, Ar);
        if (ro == 1) psh[lc] = part;
        __syncthreads();
        if (isOwner) {
            z = part + psh[lc];
            float kd = dt * tanh_f(z + w0);      // t=0, j=0: g = w0
            kdreg[0] = kd;
            ksh[0][col] = kd;
            st_async_f32(peer_ksh + (uint32_t)(0*Dd + col)*4u, kd, peer_mb + 0u);
        }
    }

    for (int t = 0; t < Tt - 1; ++t) {
        const uint32_t par = (uint32_t)(t & 1);
        const bool fst = (t == 0);

#pragma unroll
        for (int j = 0; j < 6; ++j) {
            __syncthreads();                     // bar1: own k half staged
            float part;
            if (isE) {
                part = pdot(ksh[j] + ro*HALF, Ar);
            } else {
                wait_parity(mbar_a + 8u*(uint32_t)j, par);
                if (tid == lateFirst)
                    mbar_arm(mbar_a + 8u*(uint32_t)j, HALF*4);  // re-arm next phase
                part = pdot(ksh[j] + ro*HALF, Ar);
            }
            if (ro == 1) psh[lc] = part;
            __syncthreads();                     // bar2: partials ready
            if (isOwner) {
                float vd = part + psh[lc];
                vdj[j] = vd;
                if (j < 5) {
                    float pn = z;
#pragma unroll
                    for (int i = 0; i <= j; ++i)
                        if (AT[j+1][i] != 0.0f) pn += AT[j+1][i] * vdj[i];
                    float g = fst ? (C00[j+1]*w0 + C0P[j+1]*wp)
                                  : (FM[j+1]*wm + F0[j+1]*w0 + FP[j+1]*wp);
                    float kd = dt * tanh_f(pn + g);
                    kdreg[j+1] = kd;
                    ksh[j+1][col] = kd;
                    st_async_f32(peer_ksh + (uint32_t)((j+1)*Dd + col)*4u,
                                 kd, peer_mb + 8u*(uint32_t)(j+1));
                } else {
                    xr += BT[0]*kdreg[0] + BT[2]*kdreg[2] + BT[3]*kdreg[3]
                        + BT[4]*kdreg[4] + BT[5]*kdreg[5];
                    z  += BT[0]*vdj[0] + BT[2]*vdj[2] + BT[3]*vdj[3]
                        + BT[4]*vdj[4] + BT[5]*vdj[5];
                    xtraj[(size_t)b*Tt*Dd + (size_t)(t + 1)*Dd + col] = xr;
                    wm = w0; w0 = wp;
                    if (t < Tt - 2) wp = Wb[(size_t)(t + 2)*Dd];
                    // k0 of step t+1 (g = F0[0]*w0 = w0)
                    float kd = dt * tanh_f(z + w0);
                    kdreg[0] = kd;
                    ksh[0][col] = kd;
                    st_async_f32(peer_ksh + (uint32_t)(0*Dd + col)*4u,
                                 kd, peer_mb + 0u);
                }
            }
        }
    }
    cluster_sync_();     // no CTA exits while peer st.async may be in flight
}

// Out[M,N] = A[M,K] @ B[K,N] (+ bias). 64x64 tile, BK=16, 256 thr, 4x4/thread.
__global__ void __launch_bounds__(256)
gemm_kernel(const float* __restrict__ A, const float* __restrict__ B,
            const float* __restrict__ bias, float* __restrict__ out,
            int K, int N)
{
    __shared__ float As[16][68];
    __shared__ float Bs[16][68];
    const int tid = threadIdx.x;
    const int tx = tid & 15, ty = tid >> 4;
    const int m0 = blockIdx.y * 64;
    const int n0 = blockIdx.x * 64;
    const int arow = tid >> 2, aq = tid & 3;
    const int brow = tid >> 4, bq = tid & 15;

    float acc[4][4] = {};
    for (int k0 = 0; k0 < K; k0 += 16) {
        float4 av = *(const float4*)&A[(size_t)(m0 + arow)*K + k0 + 4*aq];
        As[4*aq+0][arow] = av.x; As[4*aq+1][arow] = av.y;
        As[4*aq+2][arow] = av.z; As[4*aq+3][arow] = av.w;
        float4 bv = *(const float4*)&B[(size_t)(k0 + brow)*N + n0 + 4*bq];
        *(float4*)&Bs[brow][4*bq] = bv;
        __syncthreads();
#pragma unroll
        for (int k = 0; k < 16; ++k) {
            float a[4], bb[4];
#pragma unroll
            for (int i = 0; i < 4; ++i) a[i] = As[k][ty*4 + i];
#pragma unroll
            for (int jj = 0; jj < 4; ++jj) bb[jj] = Bs[k][tx*4 + jj];
#pragma unroll
            for (int i = 0; i < 4; ++i)
#pragma unroll
                for (int jj = 0; jj < 4; ++jj) acc[i][jj] += a[i]*bb[jj];
        }
        __syncthreads();
    }
#pragma unroll
    for (int i = 0; i < 4; ++i) {
        const int m = m0 + ty*4 + i;
#pragma unroll
        for (int jj = 0; jj < 4; ++jj) {
            const int n = n0 + tx*4 + jj;
            float v = acc[i][jj];
            if (bias) v += bias[n];
            out[(size_t)m*N + n] = v;
        }
    }
}

extern "C" void kernel_launch(void* const* d_in, const int* in_sizes, int n_in,
                              void* d_out, int out_size)
{
    const float* tarr = (const float*)d_in[0];   // (1024,)
    const float* u    = (const float*)d_in[1];   // (64,1024,128)
    const float* x0   = (const float*)d_in[2];   // (64,256)
    const float* Amat = (const float*)d_in[3];   // (256,256)
    const float* Bm   = (const float*)d_in[4];   // (128,256)
    const float* bias = (const float*)d_in[5];   // (256,)
    const float* Cm   = (const float*)d_in[6];   // (256,64)

    float* out   = (float*)d_out;
    float* xtraj = out;                              // (64,1024,256)
    float* y     = out + (size_t)Bb * Tt * Dd;       // (64,1024,64)

    float* W = nullptr;
    cudaGetSymbolAddress((void**)&W, g_W);

    // 1) W[b,t,:] = u[b,t,:] @ Bm + bias    M=65536, K=128, N=256
    gemm_kernel<<<dim3(Dd/64, (Bb*Tt)/64), 256>>>(u, Bm, bias, W, 128, Dd);

    // 2) sequential Dopri5 flow: 64 batches x 2-CTA clusters = 128 CTAs
    flow_kernel<<<2*Bb, 256>>>(tarr, x0, Amat, W, xtraj);

    // 3) y = x_traj @ C                     M=65536, K=256, N=64
    gemm_kernel<<<dim3(1, (Bb*Tt)/64), 256>>>(xtraj, Cm, nullptr, y, Dd, 64);
}

// round 11
// speedup vs baseline: 1.5196x; 1.0586x over previous
#include <cuda_runtime.h>
#include <cstdint>
#include <cstddef>

typedef unsigned long long ull;

#define Dd 256
#define Tt 1024
#define Bb 64
#define HALF 128

// scratch: W = u @ Bm + b   (64 MB)
__device__ float g_W[(size_t)Bb * Tt * Dd];

// Dopri5 tableau (compile-time constants -> FFMA immediates)
__device__ constexpr float AT[6][6] = {
  {0,0,0,0,0,0},
  {0.2f,0,0,0,0,0},
  {0.075f,0.225f,0,0,0,0},
  {0.9777777777777777f,-3.7333333333333334f,3.5555555555555554f,0,0,0},
  {2.952598689224204f,-11.595793324188386f,9.822892851699436f,-0.2908093278463649f,0,0},
  {2.8462752525252526f,-10.757575757575758f,8.906422717743473f,0.2784090909090909f,-0.27353130360205833f,0}};
__device__ constexpr float BT[6] = {0.09114583333333333f,0.0f,0.4492362982929021f,
  0.6510416666666666f,-0.3223761792452830f,0.13095238095238096f};
// Hermite drive (t>=1): g = FM*W[t-1] + F0*W[t] + FP*W[t+1]
__device__ constexpr float FM[6] = {0.f,-0.128f,-0.147f,-0.032f,-0.010973936899862826f,0.f};
__device__ constexpr float F0[6] = {1.f, 1.056f, 0.994f, 0.264f, 0.13305898491083677f,0.f};
__device__ constexpr float FP[6] = {0.f, 0.072f, 0.153f, 0.768f, 0.8779149519890261f, 1.f};
// t == 0 (first-point derivative copy): g = C00*W[0] + C0P*W[1]
__device__ constexpr float C00[6] = {1.f,0.8f,0.7f,0.2f,0.1111111111111111f,0.f};
__device__ constexpr float C0P[6] = {0.f,0.2f,0.3f,0.8f,0.8888888888888888f,1.f};

// ---------------- helpers ----------------
__device__ __forceinline__ ull pk2(float lo, float hi) {
    ull r; asm("mov.b64 %0,{%1,%2};" : "=l"(r) : "f"(lo), "f"(hi)); return r;
}
__device__ __forceinline__ void fma2(ull& d, ull a, ull b) {
    asm("fma.rn.f32x2 %0,%1,%2,%0;" : "+l"(d) : "l"(a), "l"(b));
}
__device__ __forceinline__ ull add2(ull a, ull b) {
    ull r; asm("add.rn.f32x2 %0,%1,%2;" : "=l"(r) : "l"(a), "l"(b)); return r;
}
__device__ __forceinline__ float red2(ull a) {
    float lo, hi; asm("mov.b64 {%0,%1},%2;" : "=f"(lo), "=f"(hi) : "l"(a)); return lo + hi;
}
__device__ __forceinline__ float tanh_f(float x) {
    float e = __expf(2.0f * x);
    return 1.0f - __fdividef(2.0f, e + 1.0f);
}
__device__ __forceinline__ uint32_t smem_u32(const void* p) {
    uint32_t a;
    asm("{ .reg .u64 t; cvta.to.shared.u64 t, %1; cvt.u32.u64 %0, t; }"
        : "=r"(a) : "l"(p));
    return a;
}
__device__ __forceinline__ uint32_t mapa_u32(uint32_t a, uint32_t r) {
    uint32_t d; asm("mapa.shared::cluster.u32 %0, %1, %2;" : "=r"(d) : "r"(a), "r"(r));
    return d;
}
__device__ __forceinline__ void mbar_init(uint32_t a, uint32_t cnt) {
    asm volatile("mbarrier.init.shared.b64 [%0], %1;" :: "r"(a), "r"(cnt) : "memory");
}
__device__ __forceinline__ void mbar_arm(uint32_t a, uint32_t bytes) {
    asm volatile("mbarrier.arrive.expect_tx.shared.b64 _, [%0], %1;"
                 :: "r"(a), "r"(bytes) : "memory");
}
__device__ __forceinline__ void st_async_f32(uint32_t dst, float v, uint32_t rbar) {
    asm volatile(
        "st.async.shared::cluster.mbarrier::complete_tx::bytes.f32 [%0], %1, [%2];"
        :: "r"(dst), "f"(v), "r"(rbar) : "memory");
}
__device__ __forceinline__ void wait_parity(uint32_t a, uint32_t parity) {
    asm volatile(
        "{\n\t.reg .pred P;\n\t"
        "W%=:\n\t"
        "mbarrier.try_wait.parity.acquire.cta.shared::cta.b64 P, [%0], %1, 0x989680;\n\t"
        "@!P bra W%=;\n\t}"
        :: "r"(a), "r"(parity) : "memory");
}
__device__ __forceinline__ void cluster_sync_() {
    asm volatile("barrier.cluster.arrive.aligned;" ::: "memory");
    asm volatile("barrier.cluster.wait.aligned;" ::: "memory");
}

// 128-row partial dot: rows from Ar (regs), k from smem (broadcast reads)
__device__ __forceinline__ float pdot(const float* __restrict__ kbuf,
                                      const ull (&Ar)[64])
{
    const ulonglong2* xv = (const ulonglong2*)kbuf;
    ull a0 = 0, a1 = 0, a2 = 0, a3 = 0;
#pragma unroll
    for (int q = 0; q < 32; q += 2) {
        ulonglong2 v0 = xv[q], v1 = xv[q + 1];
        fma2(a0, v0.x, Ar[2*q    ]); fma2(a1, v0.y, Ar[2*q + 1]);
        fma2(a2, v1.x, Ar[2*q + 2]); fma2(a3, v1.y, Ar[2*q + 3]);
    }
    return red2(add2(add2(a0, a1), add2(a2, a3)));
}

// ================ sequential Dopri5 flow ================
// 2-CTA cluster per batch. COLUMN-split state: CTA r owns columns
// [r*128, r*128+128). 256 threads = 128 cols x 2 row-halves (ro = tid>>7).
// A[:, own cols] register-resident. Per stage, only the owner-computed dt*k
// half (512B) crosses the fabric (st.async + complete_tx).
// Role layout (NEW): owner/kd-computer = LATE role (ro == 1^rank), so the
// thread computing kd arrives last at bar2 (near-zero barrier wait) and its
// own dot partial is in registers; EARLY threads (ro == rank) dot the
// locally-staged half during the fabric window and publish via psh.
__global__ void __launch_bounds__(256, 1) __cluster_dims__(2, 1, 1)
flow_kernel(const float* __restrict__ tarr, const float* __restrict__ x0,
            const float* __restrict__ Amat, const float* __restrict__ W,
            float* __restrict__ xtraj)
{
    __shared__ __align__(16) float ksh[6][Dd];   // staged dt*k, slot per stage
    __shared__ float psh[HALF];                  // early-half partials
    __shared__ __align__(8)  ull  mbar[6];

    const int tid = threadIdx.x;
    const int lc  = tid & (HALF - 1);
    const int ro  = tid >> 7;                    // row half this thread dots
    uint32_t rank; asm("mov.u32 %0, %%cluster_ctarank;" : "=r"(rank));
    const uint32_t peer = rank ^ 1u;
    const int b   = blockIdx.x >> 1;
    const int col = (int)rank * HALF + lc;       // owned column
    const bool isE     = (ro == (int)rank);      // early: local k half
    const bool isOwner = !isE;                   // late role computes kd
    const int armThread = (int)peer * HALF;      // first owner thread
    const float dt = tarr[1] - tarr[0];

    const uint32_t mbar_a = smem_u32(mbar);
    const uint32_t ksh_a  = smem_u32(ksh);
    const uint32_t peer_ksh = mapa_u32(ksh_a, peer);
    const uint32_t peer_mb  = mapa_u32(mbar_a, peer);

    if (tid < 6) mbar_init(mbar_a + 8u*(uint32_t)tid, 1);
    __syncthreads();
    if (tid < 6) mbar_arm(mbar_a + 8u*(uint32_t)tid, HALF*4);   // 512B/phase
    __syncthreads();
    cluster_sync_();     // armed cluster-wide before any st.async

    // A rows [ro*128, +128) of owned column -> 64 packed pairs (128 regs)
    ull Ar[64];
#pragma unroll
    for (int p = 0; p < 64; ++p)
        Ar[p] = pk2(Amat[(ro*HALF + 2*p)*Dd + col],
                    Amat[(ro*HALF + 2*p + 1)*Dd + col]);

    // owner-only state
    float xr = 0.f, z = 0.f, w0 = 0.f, wp = 0.f, wm = 0.f;
    float zacc = 0.f, xracc = 0.f;
    float kdreg[6], vdj[6];
#pragma unroll
    for (int i = 0; i < 6; ++i) { kdreg[i] = 0.f; vdj[i] = 0.f; }
    const float* Wb = W + (size_t)b*Tt*Dd + col;
    if (isOwner) {
        xr = x0[b*Dd + col];
        w0 = Wb[0]; wp = Wb[Dd];
        xtraj[(size_t)b*Tt*Dd + col] = xr;
    }

    // ---- init: z = (A^T x0)[col] (both halves local; no fabric) ----
    ksh[0][tid] = x0[b*Dd + tid];
    __syncthreads();
    {
        float part = pdot(ksh[0] + ro*HALF, Ar);
        if (isE) psh[lc] = part;
        __syncthreads();
        cluster_sync_();   // both CTAs done reading x0 from ksh[0] before ship
        if (isOwner) {
            z = part + psh[lc];
            float kd = dt * tanh_f(z + w0);      // t=0, j=0: g = w0
            kdreg[0] = kd;
            ksh[0][col] = kd;
            st_async_f32(peer_ksh + (uint32_t)(0*Dd + col)*4u, kd, peer_mb + 0u);
        }
    }

    for (int t = 0; t < Tt - 1; ++t) {
        const uint32_t par = (uint32_t)(t & 1);
        const bool fst = (t == 0);

#pragma unroll
        for (int j = 0; j < 6; ++j) {
            __syncthreads();                     // bar1: own k half staged
            float part;
            if (isE) {
                part = pdot(ksh[j] + ro*HALF, Ar);   // hidden under fabric
                psh[lc] = part;
            } else {
                wait_parity(mbar_a + 8u*(uint32_t)j, par);
                if (tid == armThread)
                    mbar_arm(mbar_a + 8u*(uint32_t)j, HALF*4);  // next phase
                part = pdot(ksh[j] + ro*HALF, Ar);
            }
            __syncthreads();                     // bar2: owner arrives last
            if (isOwner) {
                float vd = part + psh[lc];
                vdj[j] = vd;
                if (j < 5) {
                    float pn = z;
#pragma unroll
                    for (int i = 0; i <= j; ++i)
                        if (AT[j+1][i] != 0.0f) pn += AT[j+1][i] * vdj[i];
                    float g = fst ? (C00[j+1]*w0 + C0P[j+1]*wp)
                                  : (FM[j+1]*wm + F0[j+1]*w0 + FP[j+1]*wp);
                    float kd = dt * tanh_f(pn + g);
                    kdreg[j+1] = kd;
                    ksh[j+1][col] = kd;
                    st_async_f32(peer_ksh + (uint32_t)((j+1)*Dd + col)*4u,
                                 kd, peer_mb + 8u*(uint32_t)(j+1));
                    // off-chain: fold b-weights incrementally after the ship
                    if (BT[j] != 0.0f) {
                        zacc  += BT[j] * vd;
                        xracc += BT[j] * kdreg[j];
                    }
                } else {
                    // stage 5: minimal on-chain work before the k0 ship
                    z += zacc + BT[5]*vd;
                    wm = w0; w0 = wp;
                    float kd = dt * tanh_f(z + w0);   // k0 of step t+1
                    ksh[0][col] = kd;
                    st_async_f32(peer_ksh + (uint32_t)(0*Dd + col)*4u,
                                 kd, peer_mb + 0u);
                    // off-chain tail
                    xr += xracc + BT[5]*kdreg[5];
                    xtraj[(size_t)b*Tt*Dd + (size_t)(t + 1)*Dd + col] = xr;
                    kdreg[0] = kd;
                    zacc = 0.f; xracc = 0.f;
                    if (t < Tt - 2) wp = Wb[(size_t)(t + 2)*Dd];
                }
            }
        }
    }
    cluster_sync_();     // no CTA exits while peer st.async may be in flight
}

// Out[M,N] = A[M,K] @ B[K,N] (+ bias). 64x64 tile, BK=16, 256 thr, 4x4/thread.
__global__ void __launch_bounds__(256)
gemm_kernel(const float* __restrict__ A, const float* __restrict__ B,
            const float* __restrict__ bias, float* __restrict__ out,
            int K, int N)
{
    __shared__ float As[16][68];
    __shared__ float Bs[16][68];
    const int tid = threadIdx.x;
    const int tx = tid & 15, ty = tid >> 4;
    const int m0 = blockIdx.y * 64;
    const int n0 = blockIdx.x * 64;
    const int arow = tid >> 2, aq = tid & 3;
    const int brow = tid >> 4, bq = tid & 15;

    float acc[4][4] = {};
    for (int k0 = 0; k0 < K; k0 += 16) {
        float4 av = *(const float4*)&A[(size_t)(m0 + arow)*K + k0 + 4*aq];
        As[4*aq+0][arow] = av.x; As[4*aq+1][arow] = av.y;
        As[4*aq+2][arow] = av.z; As[4*aq+3][arow] = av.w;
        float4 bv = *(const float4*)&B[(size_t)(k0 + brow)*N + n0 + 4*bq];
        *(float4*)&Bs[brow][4*bq] = bv;
        __syncthreads();
#pragma unroll
        for (int k = 0; k < 16; ++k) {
            float a[4], bb[4];
#pragma unroll
            for (int i = 0; i < 4; ++i) a[i] = As[k][ty*4 + i];
#pragma unroll
            for (int jj = 0; jj < 4; ++jj) bb[jj] = Bs[k][tx*4 + jj];
#pragma unroll
            for (int i = 0; i < 4; ++i)
#pragma unroll
                for (int jj = 0; jj < 4; ++jj) acc[i][jj] += a[i]*bb[jj];
        }
        __syncthreads();
    }
#pragma unroll
    for (int i = 0; i < 4; ++i) {
        const int m = m0 + ty*4 + i;
#pragma unroll
        for (int jj = 0; jj < 4; ++jj) {
            const int n = n0 + tx*4 + jj;
            float v = acc[i][jj];
            if (bias) v += bias[n];
            out[(size_t)m*N + n] = v;
        }
    }
}

extern "C" void kernel_launch(void* const* d_in, const int* in_sizes, int n_in,
                              void* d_out, int out_size)
{
    const float* tarr = (const float*)d_in[0];   // (1024,)
    const float* u    = (const float*)d_in[1];   // (64,1024,128)
    const float* x0   = (const float*)d_in[2];   // (64,256)
    const float* Amat = (const float*)d_in[3];   // (256,256)
    const float* Bm   = (const float*)d_in[4];   // (128,256)
    const float* bias = (const float*)d_in[5];   // (256,)
    const float* Cm   = (const float*)d_in[6];   // (256,64)

    float* out   = (float*)d_out;
    float* xtraj = out;                              // (64,1024,256)
    float* y     = out + (size_t)Bb * Tt * Dd;       // (64,1024,64)

    float* W = nullptr;
    cudaGetSymbolAddress((void**)&W, g_W);

    // 1) W[b,t,:] = u[b,t,:] @ Bm + bias    M=65536, K=128, N=256
    gemm_kernel<<<dim3(Dd/64, (Bb*Tt)/64), 256>>>(u, Bm, bias, W, 128, Dd);

    // 2) sequential Dopri5 flow: 64 batches x 2-CTA clusters = 128 CTAs
    flow_kernel<<<2*Bb, 256>>>(tarr, x0, Amat, W, xtraj);

    // 3) y = x_traj @ C                     M=65536, K=256, N=64
    gemm_kernel<<<dim3(1, (Bb*Tt)/64), 256>>>(xtraj, Cm, nullptr, y, Dd, 64);
}